// round 16
// baseline (speedup 1.0000x reference)
#include <cuda_runtime.h>
#include <cuda_bf16.h>
#include <math_constants.h>

// ---------------------------------------------------------------------------
// GCNLayer_V2: trimmed-mean neighbor aggregation + linear + bias + relu
// Split kernels. R15: half-live compare-exchanges — the window-liveness
// pruner now records WHICH output of each CE is live and emits only that
// FMNMX. Dead-side writes feed no live wire, so results are bit-identical
// with ~20% fewer alu ops in the sort.
//
// Inputs (metadata order):
//   d_in[0] h      float [20000,128]
//   d_in[1] norm   float [20000,1]
//   d_in[2] weight float [128,128]
//   d_in[3] bias   float [128]
//   d_in[4] nbr    int32 [20000,32]
//   d_in[5] deg    int32 [20000]
// Output: float [20000,128] = relu(accum @ W + b)
// ---------------------------------------------------------------------------

#define NNODE 20000
#define NPAD 20032          // padded to a multiple of 64 (tail rows unused)
#define FDIM 128
#define DMAX 32

typedef unsigned long long ull;

// scratch for the aggregated features (device global: no allocation allowed)
__device__ float g_accum[NPAD * FDIM];

// ---------------------------------------------------------------------------
// Compile-time trim bound. Matches runtime floorf(__fmul_rn(n,0.45f)).
// ---------------------------------------------------------------------------
__host__ __device__ constexpr int trim_b(int n) {
    int braw = n / 2 - (1 - (n & 1));
    int bcap = (int)((float)n * 0.45f);
    int b = braw < bcap ? braw : bcap;
    return b < 1 ? 1 : b;
}
__host__ __device__ constexpr int union_lo(int nmin, int nmax) {
    int m = 1 << 30;
    for (int n = nmin; n <= nmax; ++n) { int v = trim_b(n); if (v < m) m = v; }
    return m;
}
__host__ __device__ constexpr int union_hi(int nmin, int nmax) {
    int M = 0;
    for (int n = nmin; n <= nmax; ++n) { int v = n - trim_b(n); if (v > M) M = v; }
    return M;
}
__host__ __device__ constexpr int next_pow2c(int n) {
    int p = 1;
    while (p < n) p <<= 1;
    return p;
}

// ---------------------------------------------------------------------------
// Batcher odd-even merge sort network (pow2), generated at compile time.
// ---------------------------------------------------------------------------
template <int S>
struct OEMSNet {
    int a[200];
    int b[200];
    int count;

    __host__ __device__ constexpr void cmp(int i, int j) {
        a[count] = i; b[count] = j; ++count;
    }
    __host__ __device__ constexpr void merge(int lo, int n, int r) {
        int m = r * 2;
        if (m < n) {
            merge(lo, n, m);
            merge(lo + r, n, m);
            for (int i = lo + r; i + r < lo + n; i += m) cmp(i, i + r);
        } else {
            cmp(lo, lo + r);
        }
    }
    __host__ __device__ constexpr void sort(int lo, int n) {
        if (n > 1) {
            int m = n / 2;
            sort(lo, m);
            sort(lo + m, m);
            merge(lo, n, 1);
        }
    }
    __host__ __device__ constexpr OEMSNet() : a(), b(), count(0) { sort(0, S); }
};

// ---------------------------------------------------------------------------
// Class network over NW wires, pruned twice (sentinel + window liveness),
// with per-CE half-liveness: mn[p]/mx[p] say whether the min-side (low wire)
// and/or max-side (high wire) result is consumed by any live wire. Only the
// live side is emitted; the dead side's stale value is never read.
// ---------------------------------------------------------------------------
template <int NW, int ULO, int UHI>
struct ClassNet {
    int a[200];
    int b[200];
    int mn[200];
    int mx[200];
    int count;

    __host__ __device__ constexpr ClassNet()
        : a(), b(), mn(), mx(), count(0) {
        constexpr int P = next_pow2c(NW);
        OEMSNet<P> full{};

        int ta[200] = {};
        int tb[200] = {};
        int tc = 0;
        for (int p = 0; p < full.count; ++p)
            if (full.b[p] < NW) { ta[tc] = full.a[p]; tb[tc] = full.b[p]; ++tc; }

        bool live[64] = {};
        for (int i = ULO; i < UHI; ++i) live[i] = true;
        int kmn[200] = {};
        int kmx[200] = {};
        bool keep[200] = {};
        for (int p = tc - 1; p >= 0; --p) {
            bool lmin = live[ta[p]];   // low wire receives the min
            bool lmax = live[tb[p]];   // high wire receives the max
            if (lmin || lmax) {
                keep[p] = true;
                kmn[p] = lmin ? 1 : 0;
                kmx[p] = lmax ? 1 : 0;
                live[ta[p]] = true;    // both inputs feed the live output(s)
                live[tb[p]] = true;
            }
        }
        for (int p = 0; p < tc; ++p)
            if (keep[p]) {
                a[count] = ta[p];
                b[count] = tb[p];
                mn[count] = kmn[p];
                mx[count] = kmx[p];
                ++count;
            }
    }
};

// ---------------------------------------------------------------------------
// Kernel 1: per-node, per-feature trimmed aggregation.
// Block = 128 threads (one per feature), grid = N nodes; 5 window-pruned
// class networks (I$-safe; 29 variants thrashed I$).
//
// Munge-free keys: key = h value with low 5 mantissa bits replaced by the
// slot index; FMNMX orders signed floats natively. Half-live CEs emit a
// single FMNMX. The window loop uses the key as the value (<=2^-18 rel
// perturbation) and recovers slot = bits & 31 for the norm lookup.
// Sentinel = 0x7F000000|slot (huge finite; no NaN/inf hazards).
// ---------------------------------------------------------------------------

template <int NW, int NMIN, int NMAX>
__device__ __forceinline__ float trimmed_cls(const float* __restrict__ h,
                                             const int* s_nbr,
                                             const float* s_norm,
                                             int n, int lo, int hi, int tid) {
    constexpr int ULO = union_lo(NMIN, NMAX);
    constexpr int UHI = union_hi(NMIN, NMAX);

    float key[NW];
#pragma unroll
    for (int d = 0; d < NW; ++d) {
        if (d < n) {
            int src = s_nbr[d];
            unsigned u = __float_as_uint(__ldg(&h[src * FDIM + tid]));
            key[d] = __uint_as_float((u & ~31u) | (unsigned)d);  // 1 LOP3
        } else {
            key[d] = __uint_as_float(0x7F000000u | (unsigned)d); // huge finite
        }
    }

    constexpr ClassNet<NW, ULO, UHI> net{};
#pragma unroll
    for (int p = 0; p < net.count; ++p) {
        const int i = net.a[p];
        const int l = net.b[p];
        float ki = key[i], kl = key[l];
        if (net.mn[p] && net.mx[p]) {
            key[i] = fminf(ki, kl);      // FMNMX
            key[l] = fmaxf(ki, kl);      // FMNMX
        } else if (net.mn[p]) {
            key[i] = fminf(ki, kl);      // max side dead: skip
        } else {
            key[l] = fmaxf(ki, kl);      // min side dead: skip
        }
    }

    // masked fused sum over the union window: the key IS the value
    float ts = 0.0f;
#pragma unroll
    for (int r = ULO; r < UHI; ++r) {
        float x = key[r];
        int slot = (int)(__float_as_uint(x) & 31u);
        bool sel = (r >= lo) && (r < hi);
        float kk = sel ? x : 0.0f;
        ts = fmaf(kk, s_norm[slot], ts);
    }
    return ts;
}

__global__ __launch_bounds__(FDIM)
void agg_kernel(const float* __restrict__ h,
                const float* __restrict__ norm,
                const int* __restrict__ nbr,
                const int* __restrict__ deg,
                int nnode) {
    int node = blockIdx.x;
    if (node >= nnode) return;
    int tid = threadIdx.x;

    __shared__ int s_nbr[DMAX];
    __shared__ float s_norm[DMAX];
    __shared__ int s_n;
    __shared__ float s_nd;

    if (tid < DMAX) {
        int src = nbr[node * DMAX + tid];
        s_nbr[tid] = src;
        s_norm[tid] = norm[src];
    }
    if (tid == 0) {
        s_n = deg[node];
        s_nd = norm[node];
    }
    __syncthreads();

    int n = s_n;                 // block-uniform
    float normd = s_nd;
    float self0 = h[node * FDIM + tid] * normd;

    float acc;
    if (n <= 3) {
        acc = ((float)n * self0) * normd;
    } else {
        int braw = (n >> 1) - (1 - (n & 1));
        int bcap = (int)floorf(__fmul_rn((float)n, 0.45f));
        int b = min(braw, bcap);
        b = max(b, 1);
        int lo = b, hi = n - b;

        float ts;
        if (n <= 8)
            ts = trimmed_cls<8, 4, 8>(h, s_nbr, s_norm, n, lo, hi, tid);
        else if (n <= 14)
            ts = trimmed_cls<14, 9, 14>(h, s_nbr, s_norm, n, lo, hi, tid);
        else if (n <= 20)
            ts = trimmed_cls<20, 15, 20>(h, s_nbr, s_norm, n, lo, hi, tid);
        else if (n <= 26)
            ts = trimmed_cls<26, 21, 26>(h, s_nbr, s_norm, n, lo, hi, tid);
        else
            ts = trimmed_cls<32, 27, 32>(h, s_nbr, s_norm, n, lo, hi, tid);

        acc = (ts + self0 * (float)(2 * b)) * normd;
    }
    g_accum[node * FDIM + tid] = acc;
}

// ---------------------------------------------------------------------------
// Kernel 2: out = relu(accum @ W + bias)   [R10 — measured 23.6-24.7us]
// Tile = 64 rows x 64 cols, 128 threads, 8x4 register tile per thread.
// Grid = 313 row-tiles x 2 col-halves = 626 blocks; W half in 32KB smem.
// g_accum padded to 20032 rows -> single base pointer, immediate offsets.
// f32x2-packed accumulators over column pairs + fma.rn.f32x2.
// ---------------------------------------------------------------------------

#define GT_ROWS 64
#define GT_COLS 64
#define GEMM_SMEM_BYTES (FDIM * GT_COLS * 4)   // 32 KB

__device__ __forceinline__ void fma2(ull& d, ull a, ull b) {
    asm("fma.rn.f32x2 %0, %1, %2, %0;" : "+l"(d) : "l"(a), "l"(b));
}
__device__ __forceinline__ ull dup2(float x) {
    ull r;
    asm("mov.b64 %0, {%1, %1};" : "=l"(r) : "f"(x));
    return r;
}
__device__ __forceinline__ void unpack2(float& lo, float& hi, ull v) {
    asm("mov.b64 {%0, %1}, %2;" : "=f"(lo), "=f"(hi) : "l"(v));
}

__global__ __launch_bounds__(128, 5)
void gemm_kernel(const float* __restrict__ W,
                 const float* __restrict__ bias,
                 float* __restrict__ out,
                 int nnode) {
    extern __shared__ float Ws[];      // [128][64] : W rows, this block's col half

    int tid = threadIdx.x;
    int row0 = (blockIdx.x >> 1) * GT_ROWS;
    int col0 = (blockIdx.x & 1) * GT_COLS;

    // stage this column half of W (coalesced float4: 16 float4 per W row)
    {
#pragma unroll
        for (int i = 0; i < FDIM * GT_COLS / 4 / 128; ++i) {
            int idx = tid + i * 128;
            int f = idx >> 4;          // W row
            int c4 = idx & 15;         // float4 within the half-row
            *reinterpret_cast<float4*>(Ws + f * GT_COLS + c4 * 4) =
                *reinterpret_cast<const float4*>(W + f * FDIM + col0 + c4 * 4);
        }
    }
    __syncthreads();

    int tx = tid & 15;       // column group: cols col0 + tx*4 .. +3
    int ty = tid >> 4;       // row group:    rows row0 + ty*8 .. +7

    ull acc[16];             // acc[r*2+c2] = (row ty*8+r, cols tx*4+2c2..+1)
#pragma unroll
    for (int i = 0; i < 16; ++i) acc[i] = 0ull;

    const float* abase = g_accum + (row0 + ty * 8) * FDIM;   // padded: no clamp
    const ull* wbase = reinterpret_cast<const ull*>(Ws + tx * 4);

#pragma unroll 4
    for (int f2 = 0; f2 < FDIM / 2; ++f2) {
        // A: two f-values per row as one 8B broadcast load (immediate offsets)
        float2 av[8];
#pragma unroll
        for (int r = 0; r < 8; ++r)
            av[r] = __ldg(reinterpret_cast<const float2*>(abase + r * FDIM) + f2);

        // W: column pairs for f and f+1
        ull w0[2], w1[2];
        const ull* wp0 = wbase + (2 * f2) * (GT_COLS / 2);
        const ull* wp1 = wp0 + (GT_COLS / 2);
        w0[0] = wp0[0]; w0[1] = wp0[1];
        w1[0] = wp1[0]; w1[1] = wp1[1];

#pragma unroll
        for (int r = 0; r < 8; ++r) {
            ull a0 = dup2(av[r].x);
            ull a1 = dup2(av[r].y);
#pragma unroll
            for (int c2 = 0; c2 < 2; ++c2) {
                fma2(acc[r * 2 + c2], a0, w0[c2]);
                fma2(acc[r * 2 + c2], a1, w1[c2]);
            }
        }
    }

    // epilogue: bias + relu + store
    float bcol[4];
#pragma unroll
    for (int c = 0; c < 4; ++c) bcol[c] = __ldg(&bias[col0 + tx * 4 + c]);

#pragma unroll
    for (int r = 0; r < 8; ++r) {
        int row = row0 + ty * 8 + r;
        if (row < nnode) {
            float* orow = out + row * FDIM + col0 + tx * 4;
#pragma unroll
            for (int c2 = 0; c2 < 2; ++c2) {
                float lo, hi;
                unpack2(lo, hi, acc[r * 2 + c2]);
                float2 o;
                o.x = fmaxf(lo + bcol[2 * c2], 0.0f);
                o.y = fmaxf(hi + bcol[2 * c2 + 1], 0.0f);
                *reinterpret_cast<float2*>(orow + 2 * c2) = o;
            }
        }
    }
}

// ---------------------------------------------------------------------------
// launch
// ---------------------------------------------------------------------------

extern "C" void kernel_launch(void* const* d_in, const int* in_sizes, int n_in,
                              void* d_out, int out_size) {
    const float* h    = (const float*)d_in[0];
    const float* norm = (const float*)d_in[1];
    const float* W    = (const float*)d_in[2];
    const float* bias = (const float*)d_in[3];
    const int*   nbr  = (const int*)d_in[4];
    const int*   deg  = (const int*)d_in[5];
    float* out = (float*)d_out;

    int nnode = in_sizes[5];   // 20000

    cudaFuncSetAttribute(gemm_kernel,
                         cudaFuncAttributeMaxDynamicSharedMemorySize,
                         GEMM_SMEM_BYTES);

    agg_kernel<<<nnode, FDIM>>>(h, norm, nbr, deg, nnode);

    int row_tiles = (NPAD / GT_ROWS);                 // 313
    gemm_kernel<<<row_tiles * 2, 128, GEMM_SMEM_BYTES>>>(W, bias, out, nnode);
}